// round 12
// baseline (speedup 1.0000x reference)
#include <cuda_runtime.h>
#include <cuda_bf16.h>
#include <cstdint>

// Problem constants
#define NB 4
#define NT 2048
#define NC 1024
#define NH 16
#define ND 64
#define NM (NB * NT)     // 8192 rows
#define NF (3 * NC)      // 3072 qkv features

// ---------------------------------------------------------------------------
// Scratch (__device__ globals)
// ---------------------------------------------------------------------------
__device__ __nv_bfloat16 g_qkvh[NM * NF], g_qkvl[NM * NF];
__device__ __nv_bfloat16 g_at_hi[NM * NC], g_at_lo[NM * NC];
__device__ __nv_bfloat16 g_x_hi[NM * NC],  g_x_lo[NM * NC];
__device__ __nv_bfloat16 g_wq_hi[NF * NC], g_wq_lo[NF * NC];
__device__ __nv_bfloat16 g_wp_hi[NC * NC], g_wp_lo[NC * NC];

// ---------------------------------------------------------------------------
// PTX helpers (arch-agnostic: mma.sync / ldmatrix / cp.async only)
// ---------------------------------------------------------------------------
__device__ __forceinline__ uint32_t smem_u32(const void* p) {
    uint32_t a;
    asm("{ .reg .u64 t; cvta.to.shared.u64 t, %1; cvt.u32.u64 %0, t; }"
        : "=r"(a) : "l"(p));
    return a;
}

__device__ __forceinline__ void cp_async16(uint32_t dst, const void* src) {
    asm volatile("cp.async.cg.shared.global [%0], [%1], 16;" :: "r"(dst), "l"(src));
}

__device__ __forceinline__ void ldsm4(uint32_t* r, uint32_t addr) {
    asm volatile("ldmatrix.sync.aligned.m8n8.x4.shared.b16 {%0,%1,%2,%3}, [%4];"
                 : "=r"(r[0]), "=r"(r[1]), "=r"(r[2]), "=r"(r[3]) : "r"(addr));
}

__device__ __forceinline__ void ldsm4t(uint32_t* r, uint32_t addr) {
    asm volatile("ldmatrix.sync.aligned.m8n8.x4.trans.shared.b16 {%0,%1,%2,%3}, [%4];"
                 : "=r"(r[0]), "=r"(r[1]), "=r"(r[2]), "=r"(r[3]) : "r"(addr));
}

__device__ __forceinline__ void mma_bf16(float* c, const uint32_t* a,
                                         uint32_t b0, uint32_t b1) {
    asm volatile(
        "mma.sync.aligned.m16n8k16.row.col.f32.bf16.bf16.f32 "
        "{%0,%1,%2,%3}, {%4,%5,%6,%7}, {%8,%9}, {%0,%1,%2,%3};"
        : "+f"(c[0]), "+f"(c[1]), "+f"(c[2]), "+f"(c[3])
        : "r"(a[0]), "r"(a[1]), "r"(a[2]), "r"(a[3]), "r"(b0), "r"(b1));
}

__device__ __forceinline__ void split2(float v0, float v1,
                                       uint32_t& uh, uint32_t& ul) {
    const __nv_bfloat16 h0 = __float2bfloat16(v0);
    const __nv_bfloat16 h1 = __float2bfloat16(v1);
    const float r0 = v0 - __bfloat162float(h0);
    const float r1 = v1 - __bfloat162float(h1);
    const __nv_bfloat16 l0 = __float2bfloat16(r0);
    const __nv_bfloat16 l1 = __float2bfloat16(r1);
    uh = (uint32_t)__bfloat16_as_ushort(h0) | ((uint32_t)__bfloat16_as_ushort(h1) << 16);
    ul = (uint32_t)__bfloat16_as_ushort(l0) | ((uint32_t)__bfloat16_as_ushort(l1) << 16);
}

// ---------------------------------------------------------------------------
// Split prep: fp32 [R][1024] -> hi/lo bf16 row-major.
// ---------------------------------------------------------------------------
__device__ __forceinline__ void split_body(const float* __restrict__ src,
                                           __nv_bfloat16* __restrict__ hi,
                                           __nv_bfloat16* __restrict__ lo) {
    const int r = blockIdx.x;
    const int c4 = threadIdx.x << 2;
    const float4 v = *(const float4*)(src + (size_t)r * NC + c4);
    uint2 uh, ul;
    split2(v.x, v.y, uh.x, ul.x);
    split2(v.z, v.w, uh.y, ul.y);
    *(uint2*)(hi + (size_t)r * NC + c4) = uh;
    *(uint2*)(lo + (size_t)r * NC + c4) = ul;
}

__global__ __launch_bounds__(256) void split_x(const float* __restrict__ s)  { split_body(s, g_x_hi,  g_x_lo);  }
__global__ __launch_bounds__(256) void split_wq(const float* __restrict__ s) { split_body(s, g_wq_hi, g_wq_lo); }
__global__ __launch_bounds__(256) void split_wp(const float* __restrict__ s) { split_body(s, g_wp_hi, g_wp_lo); }

// ---------------------------------------------------------------------------
// mma.sync GEMM: CTA 128x128, 512 thr / 16 warps (4x4), warp tile 32x32.
// BK=64, 2-stage cp.async double buffer (2 x 64KB smem).  [R8 config — best]
// ---------------------------------------------------------------------------
#define GSTAGE 65536
#define GEMM_SMEM (2 * GSTAGE)

template <int SPLIT_OUT>
__device__ __forceinline__ void gemm_tc_body(const __nv_bfloat16* __restrict__ Ah,
                                             const __nv_bfloat16* __restrict__ Al,
                                             const __nv_bfloat16* __restrict__ Bh,
                                             const __nv_bfloat16* __restrict__ Bl,
                                             float* __restrict__ C,
                                             __nv_bfloat16* __restrict__ Ch,
                                             __nv_bfloat16* __restrict__ Cl,
                                             int Nn) {
    extern __shared__ __align__(1024) char smem[];
    const uint32_t sb = smem_u32(smem);
    const int tid = threadIdx.x;
    const int wid = tid >> 5, lane = tid & 31;
    const int wm = wid & 3, wn = wid >> 2;      // 4 x 4 warp grid
    const int m0 = blockIdx.y << 7, n0 = blockIdx.x << 7;

    float acc[2][4][4];
#pragma unroll
    for (int i = 0; i < 2; i++)
#pragma unroll
        for (int j = 0; j < 4; j++)
#pragma unroll
            for (int k = 0; k < 4; k++) acc[i][j][k] = 0.f;

    const char* gp[4] = {
        (const char*)(Ah + (size_t)m0 * NC),
        (const char*)(Al + (size_t)m0 * NC),
        (const char*)(Bh + (size_t)n0 * NC),
        (const char*)(Bl + (size_t)n0 * NC)
    };

    // 4096 16B-chunks per stage over 512 threads -> 8 per thread.
#define LOAD_STAGE(chunk, stage) do {                                        \
    const uint32_t sbase = sb + (uint32_t)(stage) * GSTAGE;                  \
    const uint32_t koff = (uint32_t)(chunk) * 128u;                          \
    _Pragma("unroll")                                                        \
    for (int i = 0; i < 8; i++) {                                            \
        const int idx = tid + i * 512;                                       \
        const int arr = i >> 1;                                              \
        const int rem = idx & 1023;                                          \
        const int row = rem >> 3, c8 = rem & 7;                              \
        cp_async16(sbase + arr * 16384 + row * 128 + ((c8 ^ (row & 7)) << 4),\
                   gp[arr] + row * 2048 + c8 * 16 + koff);                   \
    }                                                                        \
    asm volatile("cp.async.commit_group;" ::: "memory");                     \
} while (0)

    const int a_row = (lane & 7) | (((lane >> 3) & 1) << 3);
    const int a_kc = lane >> 4;
    const int b_row = (lane & 7) + ((lane >> 4) << 3);
    const int b_kc = (lane >> 3) & 1;

    LOAD_STAGE(0, 0);

    for (int ch = 0; ch < 16; ch++) {
        if (ch + 1 < 16) {
            LOAD_STAGE(ch + 1, (ch + 1) & 1);
            asm volatile("cp.async.wait_group 1;" ::: "memory");
        } else {
            asm volatile("cp.async.wait_group 0;" ::: "memory");
        }
        __syncthreads();

        const uint32_t st = sb + (uint32_t)(ch & 1) * GSTAGE;
        const uint32_t sAh = st, sAl = st + 16384;
        const uint32_t sBh = st + 32768, sBl = st + 49152;

#pragma unroll
        for (int ks = 0; ks < 4; ks++) {
            uint32_t ah[2][4], al[2][4], bh[2][4], bl[2][4];
#pragma unroll
            for (int mi = 0; mi < 2; mi++) {
                const int r = wm * 32 + mi * 16 + a_row;
                const int kc = ks * 2 + a_kc;
                const uint32_t off = (uint32_t)(r * 128 + ((kc ^ (r & 7)) << 4));
                ldsm4(ah[mi], sAh + off);
                ldsm4(al[mi], sAl + off);
            }
#pragma unroll
            for (int gi = 0; gi < 2; gi++) {
                const int r = wn * 32 + gi * 16 + b_row;
                const int kc = ks * 2 + b_kc;
                const uint32_t off = (uint32_t)(r * 128 + ((kc ^ (r & 7)) << 4));
                ldsm4(bh[gi], sBh + off);
                ldsm4(bl[gi], sBl + off);
            }
            // Pass 1: Ah*Bh
#pragma unroll
            for (int mi = 0; mi < 2; mi++)
#pragma unroll
                for (int gi = 0; gi < 2; gi++)
#pragma unroll
                    for (int hf = 0; hf < 2; hf++)
                        mma_bf16(acc[mi][gi * 2 + hf], ah[mi],
                                 bh[gi][2 * hf], bh[gi][2 * hf + 1]);
            // Pass 2: Ah*Bl
#pragma unroll
            for (int mi = 0; mi < 2; mi++)
#pragma unroll
                for (int gi = 0; gi < 2; gi++)
#pragma unroll
                    for (int hf = 0; hf < 2; hf++)
                        mma_bf16(acc[mi][gi * 2 + hf], ah[mi],
                                 bl[gi][2 * hf], bl[gi][2 * hf + 1]);
            // Pass 3: Al*Bh
#pragma unroll
            for (int mi = 0; mi < 2; mi++)
#pragma unroll
                for (int gi = 0; gi < 2; gi++)
#pragma unroll
                    for (int hf = 0; hf < 2; hf++)
                        mma_bf16(acc[mi][gi * 2 + hf], al[mi],
                                 bh[gi][2 * hf], bh[gi][2 * hf + 1]);
        }
        __syncthreads();
    }
#undef LOAD_STAGE

    const int g4 = lane >> 2, t4 = lane & 3;
#pragma unroll
    for (int mi = 0; mi < 2; mi++) {
#pragma unroll
        for (int a = 0; a < 4; a++) {
            const int row = m0 + wm * 32 + mi * 16 + g4;
            const int col = n0 + wn * 32 + a * 8 + 2 * t4;
            if (SPLIT_OUT) {
                const float sc = (col < NC) ? 0.125f : 1.0f;   // scale Q third
                uint32_t uh, ul;
                split2(acc[mi][a][0] * sc, acc[mi][a][1] * sc, uh, ul);
                *(uint32_t*)(Ch + (size_t)row * Nn + col) = uh;
                *(uint32_t*)(Cl + (size_t)row * Nn + col) = ul;
                split2(acc[mi][a][2] * sc, acc[mi][a][3] * sc, uh, ul);
                *(uint32_t*)(Ch + (size_t)(row + 8) * Nn + col) = uh;
                *(uint32_t*)(Cl + (size_t)(row + 8) * Nn + col) = ul;
            } else {
                *(float2*)(C + (size_t)row * Nn + col) =
                    make_float2(acc[mi][a][0], acc[mi][a][1]);
                *(float2*)(C + (size_t)(row + 8) * Nn + col) =
                    make_float2(acc[mi][a][2], acc[mi][a][3]);
            }
        }
    }
}

__global__ __launch_bounds__(512) void qkv_gemm_tc() {
    gemm_tc_body<1>(g_x_hi, g_x_lo, g_wq_hi, g_wq_lo,
                    nullptr, g_qkvh, g_qkvl, NF);
}
__global__ __launch_bounds__(512) void proj_gemm_tc(float* __restrict__ out) {
    gemm_tc_body<0>(g_at_hi, g_at_lo, g_wp_hi, g_wp_lo,
                    out, nullptr, nullptr, NC);
}

// ---------------------------------------------------------------------------
// Tensor-core flash attention, 128-row q-tiles (256 thr / 8 warps).
// Warp w owns rows q0+w*16..+15; per-warp code identical to the 64-row
// version. K/V smem fill + barriers amortized over 2x MMA work.
// Causal: nchunks = 2*bx+2; generic key>row mask on the last two chunks.
// ---------------------------------------------------------------------------
#define ASTAGE 32768
#define ATTN_SMEM (2 * ASTAGE)

__global__ __launch_bounds__(256) void attn_tc_kernel()
{
    extern __shared__ __align__(1024) char asmem[];
    const uint32_t sb = smem_u32(asmem);
    const int tid = threadIdx.x;
    const int w = tid >> 5, lane = tid & 31;
    const int g = lane >> 2, t = lane & 3;
    const int bh = blockIdx.y;
    const int b = bh >> 4, h = bh & 15;
    const int q0 = blockIdx.x << 7;            // 128-row q tile
    const int t0base = b * NT;

    const int qr0 = t0base + q0 + w * 16 + g;
    const __nv_bfloat16* qh0 = g_qkvh + (size_t)qr0 * NF + h * ND;
    const __nv_bfloat16* qh1 = qh0 + 8 * NF;
    const __nv_bfloat16* ql0 = g_qkvl + (size_t)qr0 * NF + h * ND;
    const __nv_bfloat16* ql1 = ql0 + 8 * NF;

    uint32_t qa_h[4][4], qa_l[4][4];
#pragma unroll
    for (int s = 0; s < 4; s++) {
        qa_h[s][0] = *(const uint32_t*)(qh0 + s * 16 + 2 * t);
        qa_h[s][1] = *(const uint32_t*)(qh1 + s * 16 + 2 * t);
        qa_h[s][2] = *(const uint32_t*)(qh0 + s * 16 + 8 + 2 * t);
        qa_h[s][3] = *(const uint32_t*)(qh1 + s * 16 + 8 + 2 * t);
        qa_l[s][0] = *(const uint32_t*)(ql0 + s * 16 + 2 * t);
        qa_l[s][1] = *(const uint32_t*)(ql1 + s * 16 + 2 * t);
        qa_l[s][2] = *(const uint32_t*)(ql0 + s * 16 + 8 + 2 * t);
        qa_l[s][3] = *(const uint32_t*)(ql1 + s * 16 + 8 + 2 * t);
    }

    float oc[8][4];
#pragma unroll
    for (int nf = 0; nf < 8; nf++)
#pragma unroll
        for (int k = 0; k < 4; k++) oc[nf][k] = 0.f;
    float m0 = -1e30f, m1 = -1e30f, l0 = 0.f, l1 = 0.f;

    // K/V chunk loader: 2048 x 16B per chunk over 256 threads (8 per thread).
#define ALOAD(kb_, st_) do {                                                  \
    const uint32_t sbase = sb + (uint32_t)(st_) * ASTAGE;                     \
    const size_t trow = (size_t)t0base + (size_t)(kb_) * 64;                  \
    _Pragma("unroll")                                                         \
    for (int i = 0; i < 8; i++) {                                             \
        const int idx = tid + i * 256;                                        \
        const int arr = idx >> 9;                                             \
        const int rem = idx & 511;                                            \
        const int row = rem >> 3, c8 = rem & 7;                               \
        const __nv_bfloat16* src = ((arr & 1) ? g_qkvl : g_qkvh)              \
            + (trow + row) * NF + ((arr < 2) ? NC : 2 * NC) + h * ND + c8 * 8;\
        cp_async16(sbase + arr * 8192 + row * 128 + ((c8 ^ (row & 7)) << 4),  \
                   src);                                                      \
    }                                                                         \
    asm volatile("cp.async.commit_group;" ::: "memory");                      \
} while (0)

    const int nchunks = 2 * blockIdx.x + 2;
    ALOAD(0, 0);

    const int b_row = (lane & 7) + ((lane >> 4) << 3);
    const int b_kc = (lane >> 3) & 1;
    const int v_row = (lane & 7) + (((lane >> 3) & 1) << 3);
    const int v_cg = lane >> 4;

    for (int kb = 0; kb < nchunks; kb++) {
        if (kb + 1 < nchunks) {
            ALOAD(kb + 1, (kb + 1) & 1);
            asm volatile("cp.async.wait_group 1;" ::: "memory");
        } else {
            asm volatile("cp.async.wait_group 0;" ::: "memory");
        }
        __syncthreads();

        const uint32_t st = sb + (uint32_t)(kb & 1) * ASTAGE;
        const uint32_t sKh = st, sKl = st + 8192;
        const uint32_t sVh = st + 16384, sVl = st + 24576;

        float sc[8][4];
#pragma unroll
        for (int nf = 0; nf < 8; nf++)
#pragma unroll
            for (int k = 0; k < 4; k++) sc[nf][k] = 0.f;

#pragma unroll
        for (int s = 0; s < 4; s++) {
            uint32_t kbh[4][4], kbl[4][4];
#pragma unroll
            for (int gi = 0; gi < 4; gi++) {
                const int r = gi * 16 + b_row;
                const int kc = s * 2 + b_kc;
                const uint32_t off = (uint32_t)(r * 128 + ((kc ^ (r & 7)) << 4));
                ldsm4(kbh[gi], sKh + off);
                ldsm4(kbl[gi], sKl + off);
            }
#pragma unroll
            for (int gi = 0; gi < 4; gi++)
#pragma unroll
                for (int hf = 0; hf < 2; hf++)
                    mma_bf16(sc[gi * 2 + hf], qa_h[s],
                             kbh[gi][2 * hf], kbh[gi][2 * hf + 1]);
#pragma unroll
            for (int gi = 0; gi < 4; gi++)
#pragma unroll
                for (int hf = 0; hf < 2; hf++)
                    mma_bf16(sc[gi * 2 + hf], qa_h[s],
                             kbl[gi][2 * hf], kbl[gi][2 * hf + 1]);
#pragma unroll
            for (int gi = 0; gi < 4; gi++)
#pragma unroll
                for (int hf = 0; hf < 2; hf++)
                    mma_bf16(sc[gi * 2 + hf], qa_l[s],
                             kbh[gi][2 * hf], kbh[gi][2 * hf + 1]);
        }

        // causal mask on the last two chunks (diagonal band of the 128-row tile)
        if (kb >= nchunks - 2) {
            const int r0 = q0 + w * 16 + g;
            const int r1 = r0 + 8;
#pragma unroll
            for (int nf = 0; nf < 8; nf++) {
                const int c0 = kb * 64 + nf * 8 + 2 * t;
                if (c0 > r0)     sc[nf][0] = -1e30f;
                if (c0 + 1 > r0) sc[nf][1] = -1e30f;
                if (c0 > r1)     sc[nf][2] = -1e30f;
                if (c0 + 1 > r1) sc[nf][3] = -1e30f;
            }
        }

        float mx0 = -1e30f, mx1 = -1e30f;
#pragma unroll
        for (int nf = 0; nf < 8; nf++) {
            mx0 = fmaxf(mx0, fmaxf(sc[nf][0], sc[nf][1]));
            mx1 = fmaxf(mx1, fmaxf(sc[nf][2], sc[nf][3]));
        }
        mx0 = fmaxf(mx0, __shfl_xor_sync(0xffffffffu, mx0, 1));
        mx0 = fmaxf(mx0, __shfl_xor_sync(0xffffffffu, mx0, 2));
        mx1 = fmaxf(mx1, __shfl_xor_sync(0xffffffffu, mx1, 1));
        mx1 = fmaxf(mx1, __shfl_xor_sync(0xffffffffu, mx1, 2));

        const float mn0 = fmaxf(m0, mx0), mn1 = fmaxf(m1, mx1);
        const float al0 = __expf(m0 - mn0), al1 = __expf(m1 - mn1);
        float sum0 = 0.f, sum1 = 0.f;
#pragma unroll
        for (int nf = 0; nf < 8; nf++) {
            sc[nf][0] = __expf(sc[nf][0] - mn0);
            sc[nf][1] = __expf(sc[nf][1] - mn0);
            sc[nf][2] = __expf(sc[nf][2] - mn1);
            sc[nf][3] = __expf(sc[nf][3] - mn1);
            sum0 += sc[nf][0] + sc[nf][1];
            sum1 += sc[nf][2] + sc[nf][3];
        }
        sum0 += __shfl_xor_sync(0xffffffffu, sum0, 1);
        sum0 += __shfl_xor_sync(0xffffffffu, sum0, 2);
        sum1 += __shfl_xor_sync(0xffffffffu, sum1, 1);
        sum1 += __shfl_xor_sync(0xffffffffu, sum1, 2);
        l0 = l0 * al0 + sum0;  m0 = mn0;
        l1 = l1 * al1 + sum1;  m1 = mn1;
#pragma unroll
        for (int nf = 0; nf < 8; nf++) {
            oc[nf][0] *= al0; oc[nf][1] *= al0;
            oc[nf][2] *= al1; oc[nf][3] *= al1;
        }

#pragma unroll
        for (int s = 0; s < 4; s++) {
            uint32_t pa_h[4], pa_l[4];
            split2(sc[2 * s][0],     sc[2 * s][1],     pa_h[0], pa_l[0]);
            split2(sc[2 * s][2],     sc[2 * s][3],     pa_h[1], pa_l[1]);
            split2(sc[2 * s + 1][0], sc[2 * s + 1][1], pa_h[2], pa_l[2]);
            split2(sc[2 * s + 1][2], sc[2 * s + 1][3], pa_h[3], pa_l[3]);

#pragma unroll
            for (int np = 0; np < 2; np++) {
                uint32_t vbh[2][4], vbl[2][4];
#pragma unroll
                for (int ni = 0; ni < 2; ni++) {
                    const int ng = np * 2 + ni;
                    const int r = s * 16 + v_row;
                    const int kc = ng * 2 + v_cg;
                    const uint32_t off = (uint32_t)(r * 128 + ((kc ^ (r & 7)) << 4));
                    ldsm4t(vbh[ni], sVh + off);
                    ldsm4t(vbl[ni], sVl + off);
                }
#pragma unroll
                for (int ni = 0; ni < 2; ni++)
#pragma unroll
                    for (int hf = 0; hf < 2; hf++)
                        mma_bf16(oc[(np * 2 + ni) * 2 + hf], pa_h,
                                 vbh[ni][2 * hf], vbh[ni][2 * hf + 1]);
#pragma unroll
                for (int ni = 0; ni < 2; ni++)
#pragma unroll
                    for (int hf = 0; hf < 2; hf++)
                        mma_bf16(oc[(np * 2 + ni) * 2 + hf], pa_h,
                                 vbl[ni][2 * hf], vbl[ni][2 * hf + 1]);
#pragma unroll
                for (int ni = 0; ni < 2; ni++)
#pragma unroll
                    for (int hf = 0; hf < 2; hf++)
                        mma_bf16(oc[(np * 2 + ni) * 2 + hf], pa_l,
                                 vbh[ni][2 * hf], vbh[ni][2 * hf + 1]);
            }
        }
        __syncthreads();
    }
#undef ALOAD

    const float inv0 = 1.0f / l0, inv1 = 1.0f / l1;
    __nv_bfloat16* oh0 = g_at_hi + (size_t)qr0 * NC + h * ND;
    __nv_bfloat16* ol0 = g_at_lo + (size_t)qr0 * NC + h * ND;
#pragma unroll
    for (int nf = 0; nf < 8; nf++) {
        const int col = nf * 8 + 2 * t;
        uint32_t uh, ul;
        split2(oc[nf][0] * inv0, oc[nf][1] * inv0, uh, ul);
        *(uint32_t*)(oh0 + col) = uh;
        *(uint32_t*)(ol0 + col) = ul;
        split2(oc[nf][2] * inv1, oc[nf][3] * inv1, uh, ul);
        *(uint32_t*)(oh0 + 8 * NC + col) = uh;
        *(uint32_t*)(ol0 + 8 * NC + col) = ul;
    }
}

// ---------------------------------------------------------------------------
// Launch pipeline (default stream, graph-capturable)
// ---------------------------------------------------------------------------
extern "C" void kernel_launch(void* const* d_in, const int* in_sizes, int n_in,
                              void* d_out, int out_size)
{
    const float* x      = (const float*)d_in[0];
    const float* w_qkv  = (const float*)d_in[1];
    const float* w_proj = (const float*)d_in[2];
    float* out = (float*)d_out;

    cudaFuncSetAttribute(qkv_gemm_tc,
                         cudaFuncAttributeMaxDynamicSharedMemorySize, GEMM_SMEM);
    cudaFuncSetAttribute(proj_gemm_tc,
                         cudaFuncAttributeMaxDynamicSharedMemorySize, GEMM_SMEM);
    cudaFuncSetAttribute(attn_tc_kernel,
                         cudaFuncAttributeMaxDynamicSharedMemorySize, ATTN_SMEM);

    split_x<<<NM, 256>>>(x);
    split_wq<<<NF, 256>>>(w_qkv);
    split_wp<<<NC, 256>>>(w_proj);

    qkv_gemm_tc<<<dim3(NF / 128, NM / 128), 512, GEMM_SMEM>>>();

    attn_tc_kernel<<<dim3(NT / 128, NB * NH), 256, ATTN_SMEM>>>();

    proj_gemm_tc<<<dim3(NC / 128, NM / 128), 512, GEMM_SMEM>>>(out);
}

// round 14
// speedup vs baseline: 1.0580x; 1.0580x over previous
#include <cuda_runtime.h>
#include <cuda_bf16.h>
#include <cstdint>

// Problem constants
#define NB 4
#define NT 2048
#define NC 1024
#define NH 16
#define ND 64
#define NM (NB * NT)     // 8192 rows
#define NF (3 * NC)      // 3072 qkv features

// ---------------------------------------------------------------------------
// Scratch (__device__ globals)
// ---------------------------------------------------------------------------
__device__ __nv_bfloat16 g_qkvh[NM * NF], g_qkvl[NM * NF];
__device__ __nv_bfloat16 g_at_hi[NM * NC], g_at_lo[NM * NC];
__device__ __nv_bfloat16 g_x_hi[NM * NC],  g_x_lo[NM * NC];
__device__ __nv_bfloat16 g_wq_hi[NF * NC], g_wq_lo[NF * NC];
__device__ __nv_bfloat16 g_wp_hi[NC * NC], g_wp_lo[NC * NC];

// ---------------------------------------------------------------------------
// PTX helpers (arch-agnostic: mma.sync / ldmatrix / cp.async only)
// ---------------------------------------------------------------------------
__device__ __forceinline__ uint32_t smem_u32(const void* p) {
    uint32_t a;
    asm("{ .reg .u64 t; cvta.to.shared.u64 t, %1; cvt.u32.u64 %0, t; }"
        : "=r"(a) : "l"(p));
    return a;
}

__device__ __forceinline__ void cp_async16(uint32_t dst, const void* src) {
    asm volatile("cp.async.cg.shared.global [%0], [%1], 16;" :: "r"(dst), "l"(src));
}

__device__ __forceinline__ void ldsm4(uint32_t* r, uint32_t addr) {
    asm volatile("ldmatrix.sync.aligned.m8n8.x4.shared.b16 {%0,%1,%2,%3}, [%4];"
                 : "=r"(r[0]), "=r"(r[1]), "=r"(r[2]), "=r"(r[3]) : "r"(addr));
}

__device__ __forceinline__ void ldsm4t(uint32_t* r, uint32_t addr) {
    asm volatile("ldmatrix.sync.aligned.m8n8.x4.trans.shared.b16 {%0,%1,%2,%3}, [%4];"
                 : "=r"(r[0]), "=r"(r[1]), "=r"(r[2]), "=r"(r[3]) : "r"(addr));
}

__device__ __forceinline__ void mma_bf16(float* c, const uint32_t* a,
                                         uint32_t b0, uint32_t b1) {
    asm volatile(
        "mma.sync.aligned.m16n8k16.row.col.f32.bf16.bf16.f32 "
        "{%0,%1,%2,%3}, {%4,%5,%6,%7}, {%8,%9}, {%0,%1,%2,%3};"
        : "+f"(c[0]), "+f"(c[1]), "+f"(c[2]), "+f"(c[3])
        : "r"(a[0]), "r"(a[1]), "r"(a[2]), "r"(a[3]), "r"(b0), "r"(b1));
}

__device__ __forceinline__ void split2(float v0, float v1,
                                       uint32_t& uh, uint32_t& ul) {
    const __nv_bfloat16 h0 = __float2bfloat16(v0);
    const __nv_bfloat16 h1 = __float2bfloat16(v1);
    const float r0 = v0 - __bfloat162float(h0);
    const float r1 = v1 - __bfloat162float(h1);
    const __nv_bfloat16 l0 = __float2bfloat16(r0);
    const __nv_bfloat16 l1 = __float2bfloat16(r1);
    uh = (uint32_t)__bfloat16_as_ushort(h0) | ((uint32_t)__bfloat16_as_ushort(h1) << 16);
    ul = (uint32_t)__bfloat16_as_ushort(l0) | ((uint32_t)__bfloat16_as_ushort(l1) << 16);
}

// ---------------------------------------------------------------------------
// Split prep: fp32 [R][1024] -> hi/lo bf16 row-major.
// ---------------------------------------------------------------------------
__device__ __forceinline__ void split_body(const float* __restrict__ src,
                                           __nv_bfloat16* __restrict__ hi,
                                           __nv_bfloat16* __restrict__ lo) {
    const int r = blockIdx.x;
    const int c4 = threadIdx.x << 2;
    const float4 v = *(const float4*)(src + (size_t)r * NC + c4);
    uint2 uh, ul;
    split2(v.x, v.y, uh.x, ul.x);
    split2(v.z, v.w, uh.y, ul.y);
    *(uint2*)(hi + (size_t)r * NC + c4) = uh;
    *(uint2*)(lo + (size_t)r * NC + c4) = ul;
}

__global__ __launch_bounds__(256) void split_x(const float* __restrict__ s)  { split_body(s, g_x_hi,  g_x_lo);  }
__global__ __launch_bounds__(256) void split_wq(const float* __restrict__ s) { split_body(s, g_wq_hi, g_wq_lo); }
__global__ __launch_bounds__(256) void split_wp(const float* __restrict__ s) { split_body(s, g_wp_hi, g_wp_lo); }

// ---------------------------------------------------------------------------
// mma.sync GEMM: CTA 128x128, 512 thr / 16 warps (4x4), warp tile 32x32.
// BK=64, 2-stage cp.async double buffer (2 x 64KB smem).  [R8 config — best]
// ---------------------------------------------------------------------------
#define GSTAGE 65536
#define GEMM_SMEM (2 * GSTAGE)

template <int SPLIT_OUT>
__device__ __forceinline__ void gemm_tc_body(const __nv_bfloat16* __restrict__ Ah,
                                             const __nv_bfloat16* __restrict__ Al,
                                             const __nv_bfloat16* __restrict__ Bh,
                                             const __nv_bfloat16* __restrict__ Bl,
                                             float* __restrict__ C,
                                             __nv_bfloat16* __restrict__ Ch,
                                             __nv_bfloat16* __restrict__ Cl,
                                             int Nn) {
    extern __shared__ __align__(1024) char smem[];
    const uint32_t sb = smem_u32(smem);
    const int tid = threadIdx.x;
    const int wid = tid >> 5, lane = tid & 31;
    const int wm = wid & 3, wn = wid >> 2;      // 4 x 4 warp grid
    const int m0 = blockIdx.y << 7, n0 = blockIdx.x << 7;

    float acc[2][4][4];
#pragma unroll
    for (int i = 0; i < 2; i++)
#pragma unroll
        for (int j = 0; j < 4; j++)
#pragma unroll
            for (int k = 0; k < 4; k++) acc[i][j][k] = 0.f;

    const char* gp[4] = {
        (const char*)(Ah + (size_t)m0 * NC),
        (const char*)(Al + (size_t)m0 * NC),
        (const char*)(Bh + (size_t)n0 * NC),
        (const char*)(Bl + (size_t)n0 * NC)
    };

    // 4096 16B-chunks per stage over 512 threads -> 8 per thread.
#define LOAD_STAGE(chunk, stage) do {                                        \
    const uint32_t sbase = sb + (uint32_t)(stage) * GSTAGE;                  \
    const uint32_t koff = (uint32_t)(chunk) * 128u;                          \
    _Pragma("unroll")                                                        \
    for (int i = 0; i < 8; i++) {                                            \
        const int idx = tid + i * 512;                                       \
        const int arr = i >> 1;                                              \
        const int rem = idx & 1023;                                          \
        const int row = rem >> 3, c8 = rem & 7;                              \
        cp_async16(sbase + arr * 16384 + row * 128 + ((c8 ^ (row & 7)) << 4),\
                   gp[arr] + row * 2048 + c8 * 16 + koff);                   \
    }                                                                        \
    asm volatile("cp.async.commit_group;" ::: "memory");                     \
} while (0)

    const int a_row = (lane & 7) | (((lane >> 3) & 1) << 3);
    const int a_kc = lane >> 4;
    const int b_row = (lane & 7) + ((lane >> 4) << 3);
    const int b_kc = (lane >> 3) & 1;

    LOAD_STAGE(0, 0);

    for (int ch = 0; ch < 16; ch++) {
        if (ch + 1 < 16) {
            LOAD_STAGE(ch + 1, (ch + 1) & 1);
            asm volatile("cp.async.wait_group 1;" ::: "memory");
        } else {
            asm volatile("cp.async.wait_group 0;" ::: "memory");
        }
        __syncthreads();

        const uint32_t st = sb + (uint32_t)(ch & 1) * GSTAGE;
        const uint32_t sAh = st, sAl = st + 16384;
        const uint32_t sBh = st + 32768, sBl = st + 49152;

#pragma unroll
        for (int ks = 0; ks < 4; ks++) {
            uint32_t ah[2][4], al[2][4], bh[2][4], bl[2][4];
#pragma unroll
            for (int mi = 0; mi < 2; mi++) {
                const int r = wm * 32 + mi * 16 + a_row;
                const int kc = ks * 2 + a_kc;
                const uint32_t off = (uint32_t)(r * 128 + ((kc ^ (r & 7)) << 4));
                ldsm4(ah[mi], sAh + off);
                ldsm4(al[mi], sAl + off);
            }
#pragma unroll
            for (int gi = 0; gi < 2; gi++) {
                const int r = wn * 32 + gi * 16 + b_row;
                const int kc = ks * 2 + b_kc;
                const uint32_t off = (uint32_t)(r * 128 + ((kc ^ (r & 7)) << 4));
                ldsm4(bh[gi], sBh + off);
                ldsm4(bl[gi], sBl + off);
            }
            // Pass 1: Ah*Bh
#pragma unroll
            for (int mi = 0; mi < 2; mi++)
#pragma unroll
                for (int gi = 0; gi < 2; gi++)
#pragma unroll
                    for (int hf = 0; hf < 2; hf++)
                        mma_bf16(acc[mi][gi * 2 + hf], ah[mi],
                                 bh[gi][2 * hf], bh[gi][2 * hf + 1]);
            // Pass 2: Ah*Bl
#pragma unroll
            for (int mi = 0; mi < 2; mi++)
#pragma unroll
                for (int gi = 0; gi < 2; gi++)
#pragma unroll
                    for (int hf = 0; hf < 2; hf++)
                        mma_bf16(acc[mi][gi * 2 + hf], ah[mi],
                                 bl[gi][2 * hf], bl[gi][2 * hf + 1]);
            // Pass 3: Al*Bh
#pragma unroll
            for (int mi = 0; mi < 2; mi++)
#pragma unroll
                for (int gi = 0; gi < 2; gi++)
#pragma unroll
                    for (int hf = 0; hf < 2; hf++)
                        mma_bf16(acc[mi][gi * 2 + hf], al[mi],
                                 bh[gi][2 * hf], bh[gi][2 * hf + 1]);
        }
        __syncthreads();
    }
#undef LOAD_STAGE

    const int g4 = lane >> 2, t4 = lane & 3;
#pragma unroll
    for (int mi = 0; mi < 2; mi++) {
#pragma unroll
        for (int a = 0; a < 4; a++) {
            const int row = m0 + wm * 32 + mi * 16 + g4;
            const int col = n0 + wn * 32 + a * 8 + 2 * t4;
            if (SPLIT_OUT) {
                const float sc = (col < NC) ? 0.125f : 1.0f;   // scale Q third
                uint32_t uh, ul;
                split2(acc[mi][a][0] * sc, acc[mi][a][1] * sc, uh, ul);
                *(uint32_t*)(Ch + (size_t)row * Nn + col) = uh;
                *(uint32_t*)(Cl + (size_t)row * Nn + col) = ul;
                split2(acc[mi][a][2] * sc, acc[mi][a][3] * sc, uh, ul);
                *(uint32_t*)(Ch + (size_t)(row + 8) * Nn + col) = uh;
                *(uint32_t*)(Cl + (size_t)(row + 8) * Nn + col) = ul;
            } else {
                *(float2*)(C + (size_t)row * Nn + col) =
                    make_float2(acc[mi][a][0], acc[mi][a][1]);
                *(float2*)(C + (size_t)(row + 8) * Nn + col) =
                    make_float2(acc[mi][a][2], acc[mi][a][3]);
            }
        }
    }
}

__global__ __launch_bounds__(512) void qkv_gemm_tc() {
    gemm_tc_body<1>(g_x_hi, g_x_lo, g_wq_hi, g_wq_lo,
                    nullptr, g_qkvh, g_qkvl, NF);
}
__global__ __launch_bounds__(512) void proj_gemm_tc(float* __restrict__ out) {
    gemm_tc_body<0>(g_at_hi, g_at_lo, g_wp_hi, g_wp_lo,
                    out, nullptr, nullptr, NC);
}

// ---------------------------------------------------------------------------
// Tensor-core flash attention (bf16 hi/lo split, fp32 softmax). R8 structure;
// q-tile index reversed (longest CTAs launch first -> better wave packing).
// ---------------------------------------------------------------------------
#define ASTAGE 32768
#define ATTN_SMEM (2 * ASTAGE)

__global__ __launch_bounds__(128) void attn_tc_kernel()
{
    extern __shared__ __align__(1024) char asmem[];
    const uint32_t sb = smem_u32(asmem);
    const int tid = threadIdx.x;
    const int w = tid >> 5, lane = tid & 31;
    const int g = lane >> 2, t = lane & 3;
    const int bh = blockIdx.y;
    const int b = bh >> 4, h = bh & 15;
    const int qt = (int)(gridDim.x - 1 - blockIdx.x);   // longest-first remap
    const int q0 = qt << 6;
    const int t0base = b * NT;

    const int qr0 = t0base + q0 + w * 16 + g;
    const __nv_bfloat16* qh0 = g_qkvh + (size_t)qr0 * NF + h * ND;
    const __nv_bfloat16* qh1 = qh0 + 8 * NF;
    const __nv_bfloat16* ql0 = g_qkvl + (size_t)qr0 * NF + h * ND;
    const __nv_bfloat16* ql1 = ql0 + 8 * NF;

    uint32_t qa_h[4][4], qa_l[4][4];
#pragma unroll
    for (int s = 0; s < 4; s++) {
        qa_h[s][0] = *(const uint32_t*)(qh0 + s * 16 + 2 * t);
        qa_h[s][1] = *(const uint32_t*)(qh1 + s * 16 + 2 * t);
        qa_h[s][2] = *(const uint32_t*)(qh0 + s * 16 + 8 + 2 * t);
        qa_h[s][3] = *(const uint32_t*)(qh1 + s * 16 + 8 + 2 * t);
        qa_l[s][0] = *(const uint32_t*)(ql0 + s * 16 + 2 * t);
        qa_l[s][1] = *(const uint32_t*)(ql1 + s * 16 + 2 * t);
        qa_l[s][2] = *(const uint32_t*)(ql0 + s * 16 + 8 + 2 * t);
        qa_l[s][3] = *(const uint32_t*)(ql1 + s * 16 + 8 + 2 * t);
    }

    float oc[8][4];
#pragma unroll
    for (int nf = 0; nf < 8; nf++)
#pragma unroll
        for (int k = 0; k < 4; k++) oc[nf][k] = 0.f;
    float m0 = -1e30f, m1 = -1e30f, l0 = 0.f, l1 = 0.f;

#define ALOAD(kb_, st_) do {                                                  \
    const uint32_t sbase = sb + (uint32_t)(st_) * ASTAGE;                     \
    const size_t trow = (size_t)t0base + (size_t)(kb_) * 64;                  \
    _Pragma("unroll")                                                         \
    for (int i = 0; i < 16; i++) {                                            \
        const int idx = tid + i * 128;                                        \
        const int arr = idx >> 9;                                             \
        const int rem = idx & 511;                                            \
        const int row = rem >> 3, c8 = rem & 7;                               \
        const __nv_bfloat16* src = ((arr & 1) ? g_qkvl : g_qkvh)              \
            + (trow + row) * NF + ((arr < 2) ? NC : 2 * NC) + h * ND + c8 * 8;\
        cp_async16(sbase + arr * 8192 + row * 128 + ((c8 ^ (row & 7)) << 4),  \
                   src);                                                      \
    }                                                                         \
    asm volatile("cp.async.commit_group;" ::: "memory");                      \
} while (0)

    const int nchunks = qt + 1;
    ALOAD(0, 0);

    const int b_row = (lane & 7) + ((lane >> 4) << 3);
    const int b_kc = (lane >> 3) & 1;
    const int v_row = (lane & 7) + (((lane >> 3) & 1) << 3);
    const int v_cg = lane >> 4;

    for (int kb = 0; kb < nchunks; kb++) {
        if (kb + 1 < nchunks) {
            ALOAD(kb + 1, (kb + 1) & 1);
            asm volatile("cp.async.wait_group 1;" ::: "memory");
        } else {
            asm volatile("cp.async.wait_group 0;" ::: "memory");
        }
        __syncthreads();

        const uint32_t st = sb + (uint32_t)(kb & 1) * ASTAGE;
        const uint32_t sKh = st, sKl = st + 8192;
        const uint32_t sVh = st + 16384, sVl = st + 24576;

        float sc[8][4];
#pragma unroll
        for (int nf = 0; nf < 8; nf++)
#pragma unroll
            for (int k = 0; k < 4; k++) sc[nf][k] = 0.f;

#pragma unroll
        for (int s = 0; s < 4; s++) {
            uint32_t kbh[4][4], kbl[4][4];
#pragma unroll
            for (int gi = 0; gi < 4; gi++) {
                const int r = gi * 16 + b_row;
                const int kc = s * 2 + b_kc;
                const uint32_t off = (uint32_t)(r * 128 + ((kc ^ (r & 7)) << 4));
                ldsm4(kbh[gi], sKh + off);
                ldsm4(kbl[gi], sKl + off);
            }
#pragma unroll
            for (int gi = 0; gi < 4; gi++)
#pragma unroll
                for (int hf = 0; hf < 2; hf++)
                    mma_bf16(sc[gi * 2 + hf], qa_h[s],
                             kbh[gi][2 * hf], kbh[gi][2 * hf + 1]);
#pragma unroll
            for (int gi = 0; gi < 4; gi++)
#pragma unroll
                for (int hf = 0; hf < 2; hf++)
                    mma_bf16(sc[gi * 2 + hf], qa_h[s],
                             kbl[gi][2 * hf], kbl[gi][2 * hf + 1]);
#pragma unroll
            for (int gi = 0; gi < 4; gi++)
#pragma unroll
                for (int hf = 0; hf < 2; hf++)
                    mma_bf16(sc[gi * 2 + hf], qa_l[s],
                             kbh[gi][2 * hf], kbh[gi][2 * hf + 1]);
        }

        if (kb == nchunks - 1) {
            const int r0 = q0 + w * 16 + g;
            const int r1 = r0 + 8;
#pragma unroll
            for (int nf = 0; nf < 8; nf++) {
                const int c0 = kb * 64 + nf * 8 + 2 * t;
                if (c0 > r0)     sc[nf][0] = -1e30f;
                if (c0 + 1 > r0) sc[nf][1] = -1e30f;
                if (c0 > r1)     sc[nf][2] = -1e30f;
                if (c0 + 1 > r1) sc[nf][3] = -1e30f;
            }
        }

        float mx0 = -1e30f, mx1 = -1e30f;
#pragma unroll
        for (int nf = 0; nf < 8; nf++) {
            mx0 = fmaxf(mx0, fmaxf(sc[nf][0], sc[nf][1]));
            mx1 = fmaxf(mx1, fmaxf(sc[nf][2], sc[nf][3]));
        }
        mx0 = fmaxf(mx0, __shfl_xor_sync(0xffffffffu, mx0, 1));
        mx0 = fmaxf(mx0, __shfl_xor_sync(0xffffffffu, mx0, 2));
        mx1 = fmaxf(mx1, __shfl_xor_sync(0xffffffffu, mx1, 1));
        mx1 = fmaxf(mx1, __shfl_xor_sync(0xffffffffu, mx1, 2));

        const float mn0 = fmaxf(m0, mx0), mn1 = fmaxf(m1, mx1);
        const float al0 = __expf(m0 - mn0), al1 = __expf(m1 - mn1);
        float sum0 = 0.f, sum1 = 0.f;
#pragma unroll
        for (int nf = 0; nf < 8; nf++) {
            sc[nf][0] = __expf(sc[nf][0] - mn0);
            sc[nf][1] = __expf(sc[nf][1] - mn0);
            sc[nf][2] = __expf(sc[nf][2] - mn1);
            sc[nf][3] = __expf(sc[nf][3] - mn1);
            sum0 += sc[nf][0] + sc[nf][1];
            sum1 += sc[nf][2] + sc[nf][3];
        }
        sum0 += __shfl_xor_sync(0xffffffffu, sum0, 1);
        sum0 += __shfl_xor_sync(0xffffffffu, sum0, 2);
        sum1 += __shfl_xor_sync(0xffffffffu, sum1, 1);
        sum1 += __shfl_xor_sync(0xffffffffu, sum1, 2);
        l0 = l0 * al0 + sum0;  m0 = mn0;
        l1 = l1 * al1 + sum1;  m1 = mn1;
#pragma unroll
        for (int nf = 0; nf < 8; nf++) {
            oc[nf][0] *= al0; oc[nf][1] *= al0;
            oc[nf][2] *= al1; oc[nf][3] *= al1;
        }

#pragma unroll
        for (int s = 0; s < 4; s++) {
            uint32_t pa_h[4], pa_l[4];
            split2(sc[2 * s][0],     sc[2 * s][1],     pa_h[0], pa_l[0]);
            split2(sc[2 * s][2],     sc[2 * s][3],     pa_h[1], pa_l[1]);
            split2(sc[2 * s + 1][0], sc[2 * s + 1][1], pa_h[2], pa_l[2]);
            split2(sc[2 * s + 1][2], sc[2 * s + 1][3], pa_h[3], pa_l[3]);

#pragma unroll
            for (int np = 0; np < 2; np++) {
                uint32_t vbh[2][4], vbl[2][4];
#pragma unroll
                for (int ni = 0; ni < 2; ni++) {
                    const int ng = np * 2 + ni;
                    const int r = s * 16 + v_row;
                    const int kc = ng * 2 + v_cg;
                    const uint32_t off = (uint32_t)(r * 128 + ((kc ^ (r & 7)) << 4));
                    ldsm4t(vbh[ni], sVh + off);
                    ldsm4t(vbl[ni], sVl + off);
                }
#pragma unroll
                for (int ni = 0; ni < 2; ni++)
#pragma unroll
                    for (int hf = 0; hf < 2; hf++)
                        mma_bf16(oc[(np * 2 + ni) * 2 + hf], pa_h,
                                 vbh[ni][2 * hf], vbh[ni][2 * hf + 1]);
#pragma unroll
                for (int ni = 0; ni < 2; ni++)
#pragma unroll
                    for (int hf = 0; hf < 2; hf++)
                        mma_bf16(oc[(np * 2 + ni) * 2 + hf], pa_h,
                                 vbl[ni][2 * hf], vbl[ni][2 * hf + 1]);
#pragma unroll
                for (int ni = 0; ni < 2; ni++)
#pragma unroll
                    for (int hf = 0; hf < 2; hf++)
                        mma_bf16(oc[(np * 2 + ni) * 2 + hf], pa_l,
                                 vbh[ni][2 * hf], vbh[ni][2 * hf + 1]);
            }
        }
        __syncthreads();
    }
#undef ALOAD

    const float inv0 = 1.0f / l0, inv1 = 1.0f / l1;
    __nv_bfloat16* oh0 = g_at_hi + (size_t)qr0 * NC + h * ND;
    __nv_bfloat16* ol0 = g_at_lo + (size_t)qr0 * NC + h * ND;
#pragma unroll
    for (int nf = 0; nf < 8; nf++) {
        const int col = nf * 8 + 2 * t;
        uint32_t uh, ul;
        split2(oc[nf][0] * inv0, oc[nf][1] * inv0, uh, ul);
        *(uint32_t*)(oh0 + col) = uh;
        *(uint32_t*)(ol0 + col) = ul;
        split2(oc[nf][2] * inv1, oc[nf][3] * inv1, uh, ul);
        *(uint32_t*)(oh0 + 8 * NC + col) = uh;
        *(uint32_t*)(ol0 + 8 * NC + col) = ul;
    }
}

// ---------------------------------------------------------------------------
// Launch pipeline (default stream, graph-capturable)
// ---------------------------------------------------------------------------
extern "C" void kernel_launch(void* const* d_in, const int* in_sizes, int n_in,
                              void* d_out, int out_size)
{
    const float* x      = (const float*)d_in[0];
    const float* w_qkv  = (const float*)d_in[1];
    const float* w_proj = (const float*)d_in[2];
    float* out = (float*)d_out;

    cudaFuncSetAttribute(qkv_gemm_tc,
                         cudaFuncAttributeMaxDynamicSharedMemorySize, GEMM_SMEM);
    cudaFuncSetAttribute(proj_gemm_tc,
                         cudaFuncAttributeMaxDynamicSharedMemorySize, GEMM_SMEM);
    cudaFuncSetAttribute(attn_tc_kernel,
                         cudaFuncAttributeMaxDynamicSharedMemorySize, ATTN_SMEM);

    split_x<<<NM, 256>>>(x);
    split_wq<<<NF, 256>>>(w_qkv);
    split_wp<<<NC, 256>>>(w_proj);

    qkv_gemm_tc<<<dim3(NF / 128, NM / 128), 512, GEMM_SMEM>>>();

    attn_tc_kernel<<<dim3(NT / 64, NB * NH), 128, ATTN_SMEM>>>();

    proj_gemm_tc<<<dim3(NC / 128, NM / 128), 512, GEMM_SMEM>>>(out);
}

// round 15
// speedup vs baseline: 1.4127x; 1.3352x over previous
#include <cuda_runtime.h>
#include <cuda_fp16.h>
#include <cstdint>

// Problem constants
#define NB 4
#define NT 2048
#define NC 1024
#define NH 16
#define ND 64
#define NM (NB * NT)     // 8192 rows
#define NF (3 * NC)      // 3072 qkv features

// ---------------------------------------------------------------------------
// Scratch (__device__ globals). fp16 2-product scheme:
//   C = A*B  computed as  Ah*Bh + Al*Bh   (A split hi/lo fp16, B single fp16)
// Weights pre-scaled by 32 (undone in epilogue). Q scale 0.125 applied to S.
// ---------------------------------------------------------------------------
__device__ __half g_qkvh[NM * NF], g_qkvl[NM * NF];  // qkv out (A of attention)
__device__ __half g_at_h[NM * NC], g_at_l[NM * NC];  // attn out (A of proj)
__device__ __half g_x_h[NM * NC],  g_x_l[NM * NC];   // x split (A of qkv)
__device__ __half g_wq[NF * NC];                     // 32*w_qkv (B of qkv)
__device__ __half g_wp[NC * NC];                     // 32*w_proj (B of proj)

// ---------------------------------------------------------------------------
// PTX helpers (arch-agnostic: mma.sync / ldmatrix / cp.async only)
// ---------------------------------------------------------------------------
__device__ __forceinline__ uint32_t smem_u32(const void* p) {
    uint32_t a;
    asm("{ .reg .u64 t; cvta.to.shared.u64 t, %1; cvt.u32.u64 %0, t; }"
        : "=r"(a) : "l"(p));
    return a;
}

__device__ __forceinline__ void cp_async16(uint32_t dst, const void* src) {
    asm volatile("cp.async.cg.shared.global [%0], [%1], 16;" :: "r"(dst), "l"(src));
}

__device__ __forceinline__ void ldsm4(uint32_t* r, uint32_t addr) {
    asm volatile("ldmatrix.sync.aligned.m8n8.x4.shared.b16 {%0,%1,%2,%3}, [%4];"
                 : "=r"(r[0]), "=r"(r[1]), "=r"(r[2]), "=r"(r[3]) : "r"(addr));
}

__device__ __forceinline__ void ldsm4t(uint32_t* r, uint32_t addr) {
    asm volatile("ldmatrix.sync.aligned.m8n8.x4.trans.shared.b16 {%0,%1,%2,%3}, [%4];"
                 : "=r"(r[0]), "=r"(r[1]), "=r"(r[2]), "=r"(r[3]) : "r"(addr));
}

__device__ __forceinline__ void mma_fp16(float* c, const uint32_t* a,
                                         uint32_t b0, uint32_t b1) {
    asm volatile(
        "mma.sync.aligned.m16n8k16.row.col.f32.f16.f16.f32 "
        "{%0,%1,%2,%3}, {%4,%5,%6,%7}, {%8,%9}, {%0,%1,%2,%3};"
        : "+f"(c[0]), "+f"(c[1]), "+f"(c[2]), "+f"(c[3])
        : "r"(a[0]), "r"(a[1]), "r"(a[2]), "r"(a[3]), "r"(b0), "r"(b1));
}

__device__ __forceinline__ uint32_t packh(float v0, float v1) {
    const __half h0 = __float2half_rn(v0), h1 = __float2half_rn(v1);
    return (uint32_t)__half_as_ushort(h0) | ((uint32_t)__half_as_ushort(h1) << 16);
}

// hi/lo fp16 split of a float pair
__device__ __forceinline__ void split2h(float v0, float v1,
                                        uint32_t& uh, uint32_t& ul) {
    const __half h0 = __float2half_rn(v0);
    const __half h1 = __float2half_rn(v1);
    const float r0 = v0 - __half2float(h0);
    const float r1 = v1 - __half2float(h1);
    uh = (uint32_t)__half_as_ushort(h0) | ((uint32_t)__half_as_ushort(h1) << 16);
    ul = (uint32_t)__half_as_ushort(__float2half_rn(r0))
       | ((uint32_t)__half_as_ushort(__float2half_rn(r1)) << 16);
}

// ---------------------------------------------------------------------------
// Split prep
// ---------------------------------------------------------------------------
__global__ __launch_bounds__(256) void split_x(const float* __restrict__ s) {
    const int r = blockIdx.x;
    const int c4 = threadIdx.x << 2;
    const float4 v = *(const float4*)(s + (size_t)r * NC + c4);
    uint2 uh, ul;
    split2h(v.x, v.y, uh.x, ul.x);
    split2h(v.z, v.w, uh.y, ul.y);
    *(uint2*)(g_x_h + (size_t)r * NC + c4) = uh;
    *(uint2*)(g_x_l + (size_t)r * NC + c4) = ul;
}

__device__ __forceinline__ void splitw_body(const float* __restrict__ s,
                                            __half* __restrict__ dst) {
    const int r = blockIdx.x;
    const int c4 = threadIdx.x << 2;
    const float4 v = *(const float4*)(s + (size_t)r * NC + c4);
    uint2 u;
    u.x = packh(32.0f * v.x, 32.0f * v.y);
    u.y = packh(32.0f * v.z, 32.0f * v.w);
    *(uint2*)(dst + (size_t)r * NC + c4) = u;
}

__global__ __launch_bounds__(256) void split_wq(const float* __restrict__ s) { splitw_body(s, g_wq); }
__global__ __launch_bounds__(256) void split_wp(const float* __restrict__ s) { splitw_body(s, g_wp); }

// ---------------------------------------------------------------------------
// fp16 GEMM: C = A*B^T/32, A split (Ah,Al), B single (32-scaled fp16).
// CTA 128x128, 512 thr / 16 warps (4x4), warp tile 32x32, BK=64, 2-stage.
// Stage 48KB: Ah 16K @0, Al 16K @16K, Bh 16K @32K.
// ---------------------------------------------------------------------------
#define GSTAGE 49152
#define GEMM_SMEM (2 * GSTAGE)

template <int SPLIT_OUT>
__device__ __forceinline__ void gemm_tc_body(const __half* __restrict__ Ah,
                                             const __half* __restrict__ Al,
                                             const __half* __restrict__ Bh,
                                             float* __restrict__ C,
                                             __half* __restrict__ Ch,
                                             __half* __restrict__ Cl,
                                             int Nn) {
    extern __shared__ __align__(1024) char smem[];
    const uint32_t sb = smem_u32(smem);
    const int tid = threadIdx.x;
    const int wid = tid >> 5, lane = tid & 31;
    const int wm = wid & 3, wn = wid >> 2;
    const int m0 = blockIdx.y << 7, n0 = blockIdx.x << 7;

    float acc[2][4][4];
#pragma unroll
    for (int i = 0; i < 2; i++)
#pragma unroll
        for (int j = 0; j < 4; j++)
#pragma unroll
            for (int k = 0; k < 4; k++) acc[i][j][k] = 0.f;

    const char* gpAh = (const char*)(Ah + (size_t)m0 * NC);
    const char* gpAl = (const char*)(Al + (size_t)m0 * NC);
    const char* gpBh = (const char*)(Bh + (size_t)n0 * NC);

    // 3072 16B-chunks per stage over 512 threads -> 6 per thread.
#define LOAD_STAGE(chunk, stage) do {                                          \
    const uint32_t sbase = sb + (uint32_t)(stage) * GSTAGE;                    \
    const uint32_t koff = (uint32_t)(chunk) * 128u;                            \
    _Pragma("unroll")                                                          \
    for (int i = 0; i < 6; i++) {                                              \
        if (i < 4) {                                                           \
            const int arr = i >> 1;                                            \
            const int idx = tid + (i & 1) * 512;                               \
            const int row = idx >> 3, c8 = idx & 7;                            \
            cp_async16(sbase + (uint32_t)arr * 16384u + row * 128              \
                           + ((c8 ^ (row & 7)) << 4),                          \
                       (arr ? gpAl : gpAh) + (size_t)row * 2048                \
                           + c8 * 16 + koff);                                  \
        } else {                                                               \
            const int idx = tid + (i - 4) * 512;                               \
            const int row = idx >> 3, c8 = idx & 7;                            \
            cp_async16(sbase + 32768u + row * 128 + ((c8 ^ (row & 7)) << 4),   \
                       gpBh + (size_t)row * 2048 + c8 * 16 + koff);            \
        }                                                                      \
    }                                                                          \
    asm volatile("cp.async.commit_group;" ::: "memory");                       \
} while (0)

    const int a_row = (lane & 7) | (((lane >> 3) & 1) << 3);
    const int a_kc = lane >> 4;
    const int b_row = (lane & 7) + ((lane >> 4) << 3);
    const int b_kc = (lane >> 3) & 1;

    LOAD_STAGE(0, 0);

    for (int ch = 0; ch < 16; ch++) {
        if (ch + 1 < 16) {
            LOAD_STAGE(ch + 1, (ch + 1) & 1);
            asm volatile("cp.async.wait_group 1;" ::: "memory");
        } else {
            asm volatile("cp.async.wait_group 0;" ::: "memory");
        }
        __syncthreads();

        const uint32_t st = sb + (uint32_t)(ch & 1) * GSTAGE;
        const uint32_t sAh = st, sAl = st + 16384;
        const uint32_t sBh = st + 32768;

#pragma unroll
        for (int ks = 0; ks < 4; ks++) {
            uint32_t ah[2][4], al[2][4], bh[2][4];
#pragma unroll
            for (int mi = 0; mi < 2; mi++) {
                const int r = wm * 32 + mi * 16 + a_row;
                const int kc = ks * 2 + a_kc;
                const uint32_t off = (uint32_t)(r * 128 + ((kc ^ (r & 7)) << 4));
                ldsm4(ah[mi], sAh + off);
                ldsm4(al[mi], sAl + off);
            }
#pragma unroll
            for (int gi = 0; gi < 2; gi++) {
                const int r = wn * 32 + gi * 16 + b_row;
                const int kc = ks * 2 + b_kc;
                const uint32_t off = (uint32_t)(r * 128 + ((kc ^ (r & 7)) << 4));
                ldsm4(bh[gi], sBh + off);
            }
            // Pass 1: Ah*Bh (8 independent accumulators)
#pragma unroll
            for (int mi = 0; mi < 2; mi++)
#pragma unroll
                for (int gi = 0; gi < 2; gi++)
#pragma unroll
                    for (int hf = 0; hf < 2; hf++)
                        mma_fp16(acc[mi][gi * 2 + hf], ah[mi],
                                 bh[gi][2 * hf], bh[gi][2 * hf + 1]);
            // Pass 2: Al*Bh
#pragma unroll
            for (int mi = 0; mi < 2; mi++)
#pragma unroll
                for (int gi = 0; gi < 2; gi++)
#pragma unroll
                    for (int hf = 0; hf < 2; hf++)
                        mma_fp16(acc[mi][gi * 2 + hf], al[mi],
                                 bh[gi][2 * hf], bh[gi][2 * hf + 1]);
        }
        __syncthreads();
    }
#undef LOAD_STAGE

    const float os = 1.0f / 32.0f;   // undo the x32 weight pre-scale
    const int g4 = lane >> 2, t4 = lane & 3;
#pragma unroll
    for (int mi = 0; mi < 2; mi++) {
#pragma unroll
        for (int a = 0; a < 4; a++) {
            const int row = m0 + wm * 32 + mi * 16 + g4;
            const int col = n0 + wn * 32 + a * 8 + 2 * t4;
            const float v0 = acc[mi][a][0] * os, v1 = acc[mi][a][1] * os;
            const float v2 = acc[mi][a][2] * os, v3 = acc[mi][a][3] * os;
            if (SPLIT_OUT) {
                uint32_t uh, ul;
                split2h(v0, v1, uh, ul);
                *(uint32_t*)(Ch + (size_t)row * Nn + col) = uh;
                *(uint32_t*)(Cl + (size_t)row * Nn + col) = ul;
                split2h(v2, v3, uh, ul);
                *(uint32_t*)(Ch + (size_t)(row + 8) * Nn + col) = uh;
                *(uint32_t*)(Cl + (size_t)(row + 8) * Nn + col) = ul;
            } else {
                *(float2*)(C + (size_t)row * Nn + col) = make_float2(v0, v1);
                *(float2*)(C + (size_t)(row + 8) * Nn + col) = make_float2(v2, v3);
            }
        }
    }
}

__global__ __launch_bounds__(512) void qkv_gemm_tc() {
    gemm_tc_body<1>(g_x_h, g_x_l, g_wq, nullptr, g_qkvh, g_qkvl, NF);
}
__global__ __launch_bounds__(512) void proj_gemm_tc(float* __restrict__ out) {
    gemm_tc_body<0>(g_at_h, g_at_l, g_wp, out, nullptr, nullptr, NC);
}

// ---------------------------------------------------------------------------
// fp16 flash attention: Q split (registers) x K single; P split (registers)
// x V single. 2 MMAs per product. K/V stage = 16KB, double-buffered.
// Q scale 0.125 applied to S fragments. fp32 softmax.
// ---------------------------------------------------------------------------
#define ASTAGE 16384
#define ATTN_SMEM (2 * ASTAGE)

__global__ __launch_bounds__(128) void attn_tc_kernel()
{
    extern __shared__ __align__(1024) char asmem[];
    const uint32_t sb = smem_u32(asmem);
    const int tid = threadIdx.x;
    const int w = tid >> 5, lane = tid & 31;
    const int g = lane >> 2, t = lane & 3;
    const int bh = blockIdx.y;
    const int b = bh >> 4, h = bh & 15;
    const int qt = (int)(gridDim.x - 1 - blockIdx.x);   // longest-first remap
    const int q0 = qt << 6;
    const int t0base = b * NT;

    const int qr0 = t0base + q0 + w * 16 + g;
    const __half* qh0 = g_qkvh + (size_t)qr0 * NF + h * ND;
    const __half* qh1 = qh0 + 8 * NF;
    const __half* ql0 = g_qkvl + (size_t)qr0 * NF + h * ND;
    const __half* ql1 = ql0 + 8 * NF;

    uint32_t qa_h[4][4], qa_l[4][4];
#pragma unroll
    for (int s = 0; s < 4; s++) {
        qa_h[s][0] = *(const uint32_t*)(qh0 + s * 16 + 2 * t);
        qa_h[s][1] = *(const uint32_t*)(qh1 + s * 16 + 2 * t);
        qa_h[s][2] = *(const uint32_t*)(qh0 + s * 16 + 8 + 2 * t);
        qa_h[s][3] = *(const uint32_t*)(qh1 + s * 16 + 8 + 2 * t);
        qa_l[s][0] = *(const uint32_t*)(ql0 + s * 16 + 2 * t);
        qa_l[s][1] = *(const uint32_t*)(ql1 + s * 16 + 2 * t);
        qa_l[s][2] = *(const uint32_t*)(ql0 + s * 16 + 8 + 2 * t);
        qa_l[s][3] = *(const uint32_t*)(ql1 + s * 16 + 8 + 2 * t);
    }

    float oc[8][4];
#pragma unroll
    for (int nf = 0; nf < 8; nf++)
#pragma unroll
        for (int k = 0; k < 4; k++) oc[nf][k] = 0.f;
    float m0 = -1e30f, m1 = -1e30f, l0 = 0.f, l1 = 0.f;

    // K/V chunk loader: 1024 x 16B per chunk over 128 threads (8 per thread).
#define ALOAD(kb_, st_) do {                                                  \
    const uint32_t sbase = sb + (uint32_t)(st_) * ASTAGE;                     \
    const size_t trow = (size_t)t0base + (size_t)(kb_) * 64;                  \
    _Pragma("unroll")                                                         \
    for (int i = 0; i < 8; i++) {                                             \
        const int idx = tid + i * 128;                                        \
        const int arr = idx >> 9;              /* 0 = K, 1 = V */             \
        const int rem = idx & 511;                                            \
        const int row = rem >> 3, c8 = rem & 7;                               \
        const __half* src = g_qkvh + (trow + row) * NF                        \
            + (arr ? 2 * NC : NC) + h * ND + c8 * 8;                          \
        cp_async16(sbase + arr * 8192 + row * 128 + ((c8 ^ (row & 7)) << 4),  \
                   src);                                                      \
    }                                                                         \
    asm volatile("cp.async.commit_group;" ::: "memory");                      \
} while (0)

    const int nchunks = qt + 1;
    ALOAD(0, 0);

    const int b_row = (lane & 7) + ((lane >> 4) << 3);
    const int b_kc = (lane >> 3) & 1;
    const int v_row = (lane & 7) + (((lane >> 3) & 1) << 3);
    const int v_cg = lane >> 4;

    for (int kb = 0; kb < nchunks; kb++) {
        if (kb + 1 < nchunks) {
            ALOAD(kb + 1, (kb + 1) & 1);
            asm volatile("cp.async.wait_group 1;" ::: "memory");
        } else {
            asm volatile("cp.async.wait_group 0;" ::: "memory");
        }
        __syncthreads();

        const uint32_t st = sb + (uint32_t)(kb & 1) * ASTAGE;
        const uint32_t sKh = st, sVh = st + 8192;

        // ---- S = Q K^T : Qh*K then Ql*K (2 passes)
        float sc[8][4];
#pragma unroll
        for (int nf = 0; nf < 8; nf++)
#pragma unroll
            for (int k = 0; k < 4; k++) sc[nf][k] = 0.f;

#pragma unroll
        for (int s = 0; s < 4; s++) {
            uint32_t kbh[4][4];
#pragma unroll
            for (int gi = 0; gi < 4; gi++) {
                const int r = gi * 16 + b_row;
                const int kc = s * 2 + b_kc;
                ldsm4(kbh[gi], sKh + (uint32_t)(r * 128 + ((kc ^ (r & 7)) << 4)));
            }
#pragma unroll
            for (int gi = 0; gi < 4; gi++)
#pragma unroll
                for (int hf = 0; hf < 2; hf++)
                    mma_fp16(sc[gi * 2 + hf], qa_h[s],
                             kbh[gi][2 * hf], kbh[gi][2 * hf + 1]);
#pragma unroll
            for (int gi = 0; gi < 4; gi++)
#pragma unroll
                for (int hf = 0; hf < 2; hf++)
                    mma_fp16(sc[gi * 2 + hf], qa_l[s],
                             kbh[gi][2 * hf], kbh[gi][2 * hf + 1]);
        }

        // apply 1/sqrt(64) score scale
#pragma unroll
        for (int nf = 0; nf < 8; nf++)
#pragma unroll
            for (int k = 0; k < 4; k++) sc[nf][k] *= 0.125f;

        // causal mask (diagonal chunk)
        if (kb == nchunks - 1) {
            const int r0 = q0 + w * 16 + g;
            const int r1 = r0 + 8;
#pragma unroll
            for (int nf = 0; nf < 8; nf++) {
                const int c0 = kb * 64 + nf * 8 + 2 * t;
                if (c0 > r0)     sc[nf][0] = -1e30f;
                if (c0 + 1 > r0) sc[nf][1] = -1e30f;
                if (c0 > r1)     sc[nf][2] = -1e30f;
                if (c0 + 1 > r1) sc[nf][3] = -1e30f;
            }
        }

        // ---- online softmax
        float mx0 = -1e30f, mx1 = -1e30f;
#pragma unroll
        for (int nf = 0; nf < 8; nf++) {
            mx0 = fmaxf(mx0, fmaxf(sc[nf][0], sc[nf][1]));
            mx1 = fmaxf(mx1, fmaxf(sc[nf][2], sc[nf][3]));
        }
        mx0 = fmaxf(mx0, __shfl_xor_sync(0xffffffffu, mx0, 1));
        mx0 = fmaxf(mx0, __shfl_xor_sync(0xffffffffu, mx0, 2));
        mx1 = fmaxf(mx1, __shfl_xor_sync(0xffffffffu, mx1, 1));
        mx1 = fmaxf(mx1, __shfl_xor_sync(0xffffffffu, mx1, 2));

        const float mn0 = fmaxf(m0, mx0), mn1 = fmaxf(m1, mx1);
        const float al0 = __expf(m0 - mn0), al1 = __expf(m1 - mn1);
        float sum0 = 0.f, sum1 = 0.f;
#pragma unroll
        for (int nf = 0; nf < 8; nf++) {
            sc[nf][0] = __expf(sc[nf][0] - mn0);
            sc[nf][1] = __expf(sc[nf][1] - mn0);
            sc[nf][2] = __expf(sc[nf][2] - mn1);
            sc[nf][3] = __expf(sc[nf][3] - mn1);
            sum0 += sc[nf][0] + sc[nf][1];
            sum1 += sc[nf][2] + sc[nf][3];
        }
        sum0 += __shfl_xor_sync(0xffffffffu, sum0, 1);
        sum0 += __shfl_xor_sync(0xffffffffu, sum0, 2);
        sum1 += __shfl_xor_sync(0xffffffffu, sum1, 1);
        sum1 += __shfl_xor_sync(0xffffffffu, sum1, 2);
        l0 = l0 * al0 + sum0;  m0 = mn0;
        l1 = l1 * al1 + sum1;  m1 = mn1;
#pragma unroll
        for (int nf = 0; nf < 8; nf++) {
            oc[nf][0] *= al0; oc[nf][1] *= al0;
            oc[nf][2] *= al1; oc[nf][3] *= al1;
        }

        // ---- O += P V : Ph*V then Pl*V (P split in registers, V single)
#pragma unroll
        for (int s = 0; s < 4; s++) {
            uint32_t pa_h[4], pa_l[4];
            split2h(sc[2 * s][0],     sc[2 * s][1],     pa_h[0], pa_l[0]);
            split2h(sc[2 * s][2],     sc[2 * s][3],     pa_h[1], pa_l[1]);
            split2h(sc[2 * s + 1][0], sc[2 * s + 1][1], pa_h[2], pa_l[2]);
            split2h(sc[2 * s + 1][2], sc[2 * s + 1][3], pa_h[3], pa_l[3]);

#pragma unroll
            for (int np = 0; np < 2; np++) {
                uint32_t vbh[2][4];
#pragma unroll
                for (int ni = 0; ni < 2; ni++) {
                    const int ng = np * 2 + ni;
                    const int r = s * 16 + v_row;
                    const int kc = ng * 2 + v_cg;
                    ldsm4t(vbh[ni], sVh + (uint32_t)(r * 128 + ((kc ^ (r & 7)) << 4)));
                }
#pragma unroll
                for (int ni = 0; ni < 2; ni++)
#pragma unroll
                    for (int hf = 0; hf < 2; hf++)
                        mma_fp16(oc[(np * 2 + ni) * 2 + hf], pa_h,
                                 vbh[ni][2 * hf], vbh[ni][2 * hf + 1]);
#pragma unroll
                for (int ni = 0; ni < 2; ni++)
#pragma unroll
                    for (int hf = 0; hf < 2; hf++)
                        mma_fp16(oc[(np * 2 + ni) * 2 + hf], pa_l,
                                 vbh[ni][2 * hf], vbh[ni][2 * hf + 1]);
            }
        }
        __syncthreads();
    }
#undef ALOAD

    // ---- epilogue: normalize, split fp16 hi/lo (proj A operand)
    const float inv0 = 1.0f / l0, inv1 = 1.0f / l1;
    __half* oh0 = g_at_h + (size_t)qr0 * NC + h * ND;
    __half* ol0 = g_at_l + (size_t)qr0 * NC + h * ND;
#pragma unroll
    for (int nf = 0; nf < 8; nf++) {
        const int col = nf * 8 + 2 * t;
        uint32_t uh, ul;
        split2h(oc[nf][0] * inv0, oc[nf][1] * inv0, uh, ul);
        *(uint32_t*)(oh0 + col) = uh;
        *(uint32_t*)(ol0 + col) = ul;
        split2h(oc[nf][2] * inv1, oc[nf][3] * inv1, uh, ul);
        *(uint32_t*)(oh0 + 8 * NC + col) = uh;
        *(uint32_t*)(ol0 + 8 * NC + col) = ul;
    }
}

// ---------------------------------------------------------------------------
// Launch pipeline (default stream, graph-capturable)
// ---------------------------------------------------------------------------
extern "C" void kernel_launch(void* const* d_in, const int* in_sizes, int n_in,
                              void* d_out, int out_size)
{
    const float* x      = (const float*)d_in[0];
    const float* w_qkv  = (const float*)d_in[1];
    const float* w_proj = (const float*)d_in[2];
    float* out = (float*)d_out;

    cudaFuncSetAttribute(qkv_gemm_tc,
                         cudaFuncAttributeMaxDynamicSharedMemorySize, GEMM_SMEM);
    cudaFuncSetAttribute(proj_gemm_tc,
                         cudaFuncAttributeMaxDynamicSharedMemorySize, GEMM_SMEM);
    cudaFuncSetAttribute(attn_tc_kernel,
                         cudaFuncAttributeMaxDynamicSharedMemorySize, ATTN_SMEM);

    split_x<<<NM, 256>>>(x);
    split_wq<<<NF, 256>>>(w_qkv);
    split_wp<<<NC, 256>>>(w_proj);

    qkv_gemm_tc<<<dim3(NF / 128, NM / 128), 512, GEMM_SMEM>>>();

    attn_tc_kernel<<<dim3(NT / 64, NB * NH), 128, ATTN_SMEM>>>();

    proj_gemm_tc<<<dim3(NC / 128, NM / 128), 512, GEMM_SMEM>>>(out);
}